// round 4
// baseline (speedup 1.0000x reference)
#include <cuda_runtime.h>
#include <math.h>

#define BB 2
#define NN 2048
#define KK 48
#define CC 128
#define FFD 512
#define BN (BB * NN)          // 4096
#define EPSLN 1e-5f
#define INV_SCALE (1.0f / 30.0f)

// Scratch (device globals: allocation-free rule)
__device__ float g_Pa[BN * CC];   // h_V @ W1a + b1   (per node)
__device__ float g_Pc[BN * CC];   // h_V @ W1c        (per node)
__device__ float g_dh[BN * CC];   // masked edge-message sum per node

__device__ __forceinline__ float gelu_f(float x) {
    return 0.5f * x * (1.0f + erff(x * 0.70710678118654752f));
}

// Register-tiled GEMM inner product:
//   acc[i][j] += sum_k X[r0+i][k] * W[k][c0+j],  K = 128, c0 = lane*4
// X rows have stride (xstride4 float4s); W is 128x128 row-major in SMEM.
template <int R>
__device__ __forceinline__ void mm_tile(float acc[R][4], const float* Xs, int xstride4,
                                        const float* Ws, int r0, int lane) {
    const float4* X4 = (const float4*)Xs;
    const float4* W4 = (const float4*)Ws;
#pragma unroll 4
    for (int kq = 0; kq < 32; ++kq) {
        float4 w0 = W4[(4 * kq + 0) * 32 + lane];
        float4 w1 = W4[(4 * kq + 1) * 32 + lane];
        float4 w2 = W4[(4 * kq + 2) * 32 + lane];
        float4 w3 = W4[(4 * kq + 3) * 32 + lane];
#pragma unroll
        for (int i = 0; i < R; ++i) {
            float4 x = X4[(r0 + i) * xstride4 + kq];
            acc[i][0] = fmaf(x.x, w0.x, acc[i][0]);
            acc[i][1] = fmaf(x.x, w0.y, acc[i][1]);
            acc[i][2] = fmaf(x.x, w0.z, acc[i][2]);
            acc[i][3] = fmaf(x.x, w0.w, acc[i][3]);
            acc[i][0] = fmaf(x.y, w1.x, acc[i][0]);
            acc[i][1] = fmaf(x.y, w1.y, acc[i][1]);
            acc[i][2] = fmaf(x.y, w1.z, acc[i][2]);
            acc[i][3] = fmaf(x.y, w1.w, acc[i][3]);
            acc[i][0] = fmaf(x.z, w2.x, acc[i][0]);
            acc[i][1] = fmaf(x.z, w2.y, acc[i][1]);
            acc[i][2] = fmaf(x.z, w2.z, acc[i][2]);
            acc[i][3] = fmaf(x.z, w2.w, acc[i][3]);
            acc[i][0] = fmaf(x.w, w3.x, acc[i][0]);
            acc[i][1] = fmaf(x.w, w3.y, acc[i][1]);
            acc[i][2] = fmaf(x.w, w3.z, acc[i][2]);
            acc[i][3] = fmaf(x.w, w3.w, acc[i][3]);
        }
    }
}

// ---------------------------------------------------------------------------
// Node precompute: Pa = hV @ W1[0:128] + b1 ; Pc = hV @ W1[256:384]
// grid = 128 blocks x 32 nodes, 512 threads. SMEM: Vs 16KB + Ws 64KB.
// ---------------------------------------------------------------------------
__global__ void __launch_bounds__(512) nodepre_kernel(
    const float* __restrict__ hV, const float* __restrict__ W1,
    const float* __restrict__ b1) {
    extern __shared__ float sm[];
    float* Vs = sm;           // 32*128
    float* Ws = sm + 4096;    // 128*128
    int tid = threadIdx.x, lane = tid & 31, warp = tid >> 5;
    size_t base = (size_t)blockIdx.x * 32 * CC;

    {
        const float4* src = (const float4*)(hV + base);
        float4* dst = (float4*)Vs;
#pragma unroll
        for (int e = 0; e < 2; ++e) dst[tid + 512 * e] = src[tid + 512 * e];
    }
    {
        const float4* src = (const float4*)W1;  // W1a
        float4* dst = (float4*)Ws;
#pragma unroll
        for (int e = 0; e < 8; ++e) dst[tid + 512 * e] = src[tid + 512 * e];
    }
    __syncthreads();

    int r0 = warp * 2, c0 = lane * 4;
    float acc[2][4];
#pragma unroll
    for (int j = 0; j < 4; ++j) {
        float b = b1[c0 + j];
        acc[0][j] = b; acc[1][j] = b;
    }
    mm_tile<2>(acc, Vs, 32, Ws, r0, lane);
#pragma unroll
    for (int i = 0; i < 2; ++i)
#pragma unroll
        for (int j = 0; j < 4; ++j)
            g_Pa[base + (size_t)(r0 + i) * CC + c0 + j] = acc[i][j];
    __syncthreads();
    {
        const float4* src = (const float4*)(W1 + 2 * CC * CC);  // W1c
        float4* dst = (float4*)Ws;
#pragma unroll
        for (int e = 0; e < 8; ++e) dst[tid + 512 * e] = src[tid + 512 * e];
    }
    __syncthreads();
#pragma unroll
    for (int i = 0; i < 2; ++i)
#pragma unroll
        for (int j = 0; j < 4; ++j) acc[i][j] = 0.0f;
    mm_tile<2>(acc, Vs, 32, Ws, r0, lane);
#pragma unroll
    for (int i = 0; i < 2; ++i)
#pragma unroll
        for (int j = 0; j < 4; ++j)
            g_Pc[base + (size_t)(r0 + i) * CC + c0 + j] = acc[i][j];
}

// ---------------------------------------------------------------------------
// Edge MLP. One block per node (grid = 4096), 512 threads.
// SMEM: Es/As/Bs (48x128 each) + Ws (128x128) = 136KB dynamic.
// EDGE_OUT=false: masked sum over K -> g_dh.   EDGE_OUT=true: LN(hE+msg) -> out.
// ---------------------------------------------------------------------------
template <bool EDGE_OUT>
__global__ void __launch_bounds__(512) edge_kernel(
    const float* __restrict__ h_E, const int* __restrict__ E_idx,
    const float* __restrict__ mask_attend,
    const float* __restrict__ W1b,                       // 128x128 (middle slab)
    const float* __restrict__ W2_w, const float* __restrict__ W2_b,
    const float* __restrict__ W3_w, const float* __restrict__ W3_b,
    const float* __restrict__ g3, const float* __restrict__ b3,
    float* __restrict__ out) {
    extern __shared__ float sm[];
    float* Es = sm;            // 6144
    float* As = sm + 6144;     // 6144
    float* Bs = sm + 12288;    // 6144
    float* Ws = sm + 18432;    // 16384
    __shared__ int s_idx[KK];
    __shared__ float s_mask[KK];
    __shared__ float s_pa[CC];

    int tid = threadIdx.x, lane = tid & 31, warp = tid >> 5;
    int n = blockIdx.x;
    size_t ebase = (size_t)n * (KK * CC);

    if (tid < KK) {
        s_idx[tid] = E_idx[n * KK + tid];
        s_mask[tid] = mask_attend[n * KK + tid];
    }
    if (tid < CC) s_pa[tid] = g_Pa[(size_t)n * CC + tid];
    {
        const float4* src = (const float4*)(h_E + ebase);
        float4* dst = (float4*)Es;
#pragma unroll
        for (int e = 0; e < 3; ++e) dst[tid + 512 * e] = src[tid + 512 * e];
    }
    {
        const float4* src = (const float4*)W1b;
        float4* dst = (float4*)Ws;
#pragma unroll
        for (int e = 0; e < 8; ++e) dst[tid + 512 * e] = src[tid + 512 * e];
    }
    __syncthreads();

    // As = Pa[n] (+b1 already) + Pc[neighbor]
    int gb = (n >> 11) * NN;
#pragma unroll
    for (int e = tid; e < KK * CC; e += 512) {
        int r = e >> 7, c = e & 127;
        As[e] = s_pa[c] + g_Pc[(size_t)(gb + s_idx[r]) * CC + c];
    }
    __syncthreads();

    int r0 = warp * 3, c0 = lane * 4;

    // ---- layer 1: H1 = gelu(As + Es @ W1b) -> As
    float acc[3][4];
#pragma unroll
    for (int i = 0; i < 3; ++i)
#pragma unroll
        for (int j = 0; j < 4; ++j) acc[i][j] = As[(r0 + i) * CC + c0 + j];
    mm_tile<3>(acc, Es, 32, Ws, r0, lane);
#pragma unroll
    for (int i = 0; i < 3; ++i)
#pragma unroll
        for (int j = 0; j < 4; ++j) As[(r0 + i) * CC + c0 + j] = gelu_f(acc[i][j]);
    __syncthreads();

    // ---- layer 2: H2 = gelu(b2 + H1 @ W2) -> Bs
    {
        const float4* src = (const float4*)W2_w;
        float4* dst = (float4*)Ws;
#pragma unroll
        for (int e = 0; e < 8; ++e) dst[tid + 512 * e] = src[tid + 512 * e];
    }
    __syncthreads();
#pragma unroll
    for (int j = 0; j < 4; ++j) {
        float b = W2_b[c0 + j];
#pragma unroll
        for (int i = 0; i < 3; ++i) acc[i][j] = b;
    }
    mm_tile<3>(acc, As, 32, Ws, r0, lane);
#pragma unroll
    for (int i = 0; i < 3; ++i)
#pragma unroll
        for (int j = 0; j < 4; ++j) Bs[(r0 + i) * CC + c0 + j] = gelu_f(acc[i][j]);
    __syncthreads();

    // ---- layer 3: H3 = b3w + H2 @ W3
    {
        const float4* src = (const float4*)W3_w;
        float4* dst = (float4*)Ws;
#pragma unroll
        for (int e = 0; e < 8; ++e) dst[tid + 512 * e] = src[tid + 512 * e];
    }
    __syncthreads();
#pragma unroll
    for (int j = 0; j < 4; ++j) {
        float b = W3_b[c0 + j];
#pragma unroll
        for (int i = 0; i < 3; ++i) acc[i][j] = b;
    }
    mm_tile<3>(acc, Bs, 32, Ws, r0, lane);

    if (!EDGE_OUT) {
        // masked sum over K -> g_dh[n]
#pragma unroll
        for (int i = 0; i < 3; ++i)
#pragma unroll
            for (int j = 0; j < 4; ++j)
                As[(r0 + i) * CC + c0 + j] = s_mask[r0 + i] * acc[i][j];
        __syncthreads();
        if (tid < CC) {
            float s = 0.0f;
#pragma unroll
            for (int r = 0; r < KK; ++r) s += As[r * CC + tid];
            g_dh[(size_t)n * CC + tid] = s;
        }
    } else {
        // LN(h_E + msg) per edge row (row spread across the warp: 32 lanes x 4)
#pragma unroll
        for (int i = 0; i < 3; ++i) {
            float v0 = acc[i][0] + Es[(r0 + i) * CC + c0 + 0];
            float v1 = acc[i][1] + Es[(r0 + i) * CC + c0 + 1];
            float v2 = acc[i][2] + Es[(r0 + i) * CC + c0 + 2];
            float v3 = acc[i][3] + Es[(r0 + i) * CC + c0 + 3];
            float s = v0 + v1 + v2 + v3;
            float q = v0 * v0 + v1 * v1 + v2 * v2 + v3 * v3;
#pragma unroll
            for (int off = 16; off; off >>= 1) {
                s += __shfl_xor_sync(0xffffffffu, s, off);
                q += __shfl_xor_sync(0xffffffffu, q, off);
            }
            float mean = s * (1.0f / 128.0f);
            float var = q * (1.0f / 128.0f) - mean * mean;
            float rs = rsqrtf(var + EPSLN);
            float4 o;
            o.x = g3[c0 + 0] * (v0 - mean) * rs + b3[c0 + 0];
            o.y = g3[c0 + 1] * (v1 - mean) * rs + b3[c0 + 1];
            o.z = g3[c0 + 2] * (v2 - mean) * rs + b3[c0 + 2];
            o.w = g3[c0 + 3] * (v3 - mean) * rs + b3[c0 + 3];
            ((float4*)(out + ebase + (size_t)(r0 + i) * CC))[lane] = o;
        }
    }
}

// ---------------------------------------------------------------------------
// Node update: LN1(hV + dh/30) -> FFN -> LN2 -> mask. 128 blocks x 32 nodes.
// SMEM: V1s 16KB + Ts 64KB + Ws 64KB = 144KB.
// ---------------------------------------------------------------------------
__global__ void __launch_bounds__(512) ffn_kernel(
    const float* __restrict__ hV,
    const float* __restrict__ Win_w, const float* __restrict__ Win_b,
    const float* __restrict__ Wout_w, const float* __restrict__ Wout_b,
    const float* __restrict__ g1, const float* __restrict__ b1,
    const float* __restrict__ g2, const float* __restrict__ b2,
    const float* __restrict__ mask_V, float* __restrict__ out) {
    extern __shared__ float sm[];
    float* V1s = sm;                  // 32*128
    float* Ts = sm + 4096;            // 32*512
    float* Ws = sm + 4096 + 16384;    // 128*128
    int tid = threadIdx.x, lane = tid & 31, warp = tid >> 5;
    size_t base = (size_t)blockIdx.x * 32 * CC;
    int c0 = lane * 4;
    int r0 = warp * 2;

    // phase 1: x = hV + dh/30 ; V1 = LN(x; g1,b1)
#pragma unroll
    for (int i = 0; i < 2; ++i) {
        int r = r0 + i;
        float4 xv = *(const float4*)(hV + base + (size_t)r * CC + c0);
        float4 dv = *(const float4*)(&g_dh[base + (size_t)r * CC + c0]);
        float x0 = xv.x + dv.x * INV_SCALE;
        float x1 = xv.y + dv.y * INV_SCALE;
        float x2 = xv.z + dv.z * INV_SCALE;
        float x3 = xv.w + dv.w * INV_SCALE;
        float s = x0 + x1 + x2 + x3;
        float q = x0 * x0 + x1 * x1 + x2 * x2 + x3 * x3;
#pragma unroll
        for (int off = 16; off; off >>= 1) {
            s += __shfl_xor_sync(0xffffffffu, s, off);
            q += __shfl_xor_sync(0xffffffffu, q, off);
        }
        float mean = s * (1.0f / 128.0f);
        float var = q * (1.0f / 128.0f) - mean * mean;
        float rs = rsqrtf(var + EPSLN);
        float4 o;
        o.x = g1[c0 + 0] * (x0 - mean) * rs + b1[c0 + 0];
        o.y = g1[c0 + 1] * (x1 - mean) * rs + b1[c0 + 1];
        o.z = g1[c0 + 2] * (x2 - mean) * rs + b1[c0 + 2];
        o.w = g1[c0 + 3] * (x3 - mean) * rs + b1[c0 + 3];
        *(float4*)(V1s + r * CC + c0) = o;
    }
    __syncthreads();

    // phase 2: T = gelu(V1 @ Win + bin), column tiles of 128
    for (int ct = 0; ct < 4; ++ct) {
        if (ct) __syncthreads();
        for (int e = tid; e < 4096; e += 512) {
            int k = e >> 5, cq = e & 31;
            ((float4*)Ws)[e] = ((const float4*)Win_w)[k * 128 + ct * 32 + cq];
        }
        __syncthreads();
        float acc[2][4];
#pragma unroll
        for (int j = 0; j < 4; ++j) {
            float b = Win_b[ct * 128 + c0 + j];
            acc[0][j] = b; acc[1][j] = b;
        }
        mm_tile<2>(acc, V1s, 32, Ws, r0, lane);
#pragma unroll
        for (int i = 0; i < 2; ++i)
#pragma unroll
            for (int j = 0; j < 4; ++j)
                Ts[(r0 + i) * FFD + ct * 128 + c0 + j] = gelu_f(acc[i][j]);
    }
    __syncthreads();

    // phase 3: Y = T @ Wout + bout, k tiles of 128
    float acc[2][4];
#pragma unroll
    for (int j = 0; j < 4; ++j) {
        float b = Wout_b[c0 + j];
        acc[0][j] = b; acc[1][j] = b;
    }
    for (int kt = 0; kt < 4; ++kt) {
        if (kt) __syncthreads();
        for (int e = tid; e < 4096; e += 512)
            ((float4*)Ws)[e] = ((const float4*)Wout_w)[kt * 4096 + e];
        __syncthreads();
        mm_tile<2>(acc, Ts + kt * 128, 128, Ws, r0, lane);
    }

    // phase 4: LN2(V1 + Y) * mask_V
#pragma unroll
    for (int i = 0; i < 2; ++i) {
        int r = r0 + i;
        float v0 = V1s[r * CC + c0 + 0] + acc[i][0];
        float v1 = V1s[r * CC + c0 + 1] + acc[i][1];
        float v2 = V1s[r * CC + c0 + 2] + acc[i][2];
        float v3 = V1s[r * CC + c0 + 3] + acc[i][3];
        float s = v0 + v1 + v2 + v3;
        float q = v0 * v0 + v1 * v1 + v2 * v2 + v3 * v3;
#pragma unroll
        for (int off = 16; off; off >>= 1) {
            s += __shfl_xor_sync(0xffffffffu, s, off);
            q += __shfl_xor_sync(0xffffffffu, q, off);
        }
        float mean = s * (1.0f / 128.0f);
        float var = q * (1.0f / 128.0f) - mean * mean;
        float rs = rsqrtf(var + EPSLN);
        float mv = mask_V[blockIdx.x * 32 + r];
        float4 o;
        o.x = (g2[c0 + 0] * (v0 - mean) * rs + b2[c0 + 0]) * mv;
        o.y = (g2[c0 + 1] * (v1 - mean) * rs + b2[c0 + 1]) * mv;
        o.z = (g2[c0 + 2] * (v2 - mean) * rs + b2[c0 + 2]) * mv;
        o.w = (g2[c0 + 3] * (v3 - mean) * rs + b2[c0 + 3]) * mv;
        *(float4*)(out + base + (size_t)r * CC + c0) = o;
    }
}

// ---------------------------------------------------------------------------
extern "C" void kernel_launch(void* const* d_in, const int* in_sizes, int n_in,
                              void* d_out, int out_size) {
    const float* h_V = (const float*)d_in[0];
    const float* h_E = (const float*)d_in[1];
    const int* E_idx = (const int*)d_in[2];
    const float* mask_V = (const float*)d_in[3];
    const float* mask_attend = (const float*)d_in[4];
    const float* W1_w = (const float*)d_in[5];
    const float* W1_b = (const float*)d_in[6];
    const float* W2_w = (const float*)d_in[7];
    const float* W2_b = (const float*)d_in[8];
    const float* W3_w = (const float*)d_in[9];
    const float* W3_b = (const float*)d_in[10];
    const float* W11_w = (const float*)d_in[11];
    const float* W11_b = (const float*)d_in[12];
    const float* W12_w = (const float*)d_in[13];
    const float* W12_b = (const float*)d_in[14];
    const float* W13_w = (const float*)d_in[15];
    const float* W13_b = (const float*)d_in[16];
    const float* Win_w = (const float*)d_in[17];
    const float* Win_b = (const float*)d_in[18];
    const float* Wout_w = (const float*)d_in[19];
    const float* Wout_b = (const float*)d_in[20];
    const float* g1 = (const float*)d_in[21];
    const float* b1 = (const float*)d_in[22];
    const float* g2 = (const float*)d_in[23];
    const float* b2 = (const float*)d_in[24];
    const float* g3 = (const float*)d_in[25];
    const float* b3 = (const float*)d_in[26];

    float* out_hV = (float*)d_out;
    float* out_hE = out_hV + (size_t)BN * CC;

    const int SMEM_PRE = (4096 + 16384) * 4;          // 80 KB
    const int SMEM_EDGE = (3 * 6144 + 16384) * 4;     // 136 KB
    const int SMEM_FFN = (4096 + 16384 + 16384) * 4;  // 144 KB

    cudaFuncSetAttribute(nodepre_kernel, cudaFuncAttributeMaxDynamicSharedMemorySize, SMEM_PRE);
    cudaFuncSetAttribute(edge_kernel<false>, cudaFuncAttributeMaxDynamicSharedMemorySize, SMEM_EDGE);
    cudaFuncSetAttribute(edge_kernel<true>, cudaFuncAttributeMaxDynamicSharedMemorySize, SMEM_EDGE);
    cudaFuncSetAttribute(ffn_kernel, cudaFuncAttributeMaxDynamicSharedMemorySize, SMEM_FFN);

    // 1) node precompute for edge-MLP #1
    nodepre_kernel<<<BN / 32, 512, SMEM_PRE>>>(h_V, W1_w, W1_b);
    // 2) edge MLP #1 + masked sum over K
    edge_kernel<false><<<BN, 512, SMEM_EDGE>>>(h_E, E_idx, mask_attend,
                                               W1_w + CC * CC, W2_w, W2_b, W3_w, W3_b,
                                               g3, b3, out_hE);
    // 3) node residual + LN1 + FFN + LN2 + mask -> out_hV
    ffn_kernel<<<BN / 32, 512, SMEM_FFN>>>(h_V, Win_w, Win_b, Wout_w, Wout_b,
                                           g1, b1, g2, b2, mask_V, out_hV);
    // 4) node precompute for edge-MLP #2 (uses updated h_V)
    nodepre_kernel<<<BN / 32, 512, SMEM_PRE>>>(out_hV, W11_w, W11_b);
    // 5) edge MLP #2 + residual + LN3 -> out_hE
    edge_kernel<true><<<BN, 512, SMEM_EDGE>>>(h_E, E_idx, mask_attend,
                                              W11_w + CC * CC, W12_w, W12_b, W13_w, W13_b,
                                              g3, b3, out_hE);
}

// round 6
// speedup vs baseline: 2.2596x; 2.2596x over previous
#include <cuda_runtime.h>
#include <cuda_bf16.h>
#include <math.h>
#include <stdint.h>

#define BB 2
#define NN 2048
#define KK 48
#define CC 128
#define FFD 512
#define BN (BB * NN)
#define EPSLN 1e-5f
#define INV_SCALE (1.0f / 30.0f)

// ---------------- device scratch ----------------
__device__ float g_Pa[BN * CC];   // h_V @ W1a + b1
__device__ float g_Pc[BN * CC];   // h_V @ W1c
__device__ float g_dh[BN * CC];   // masked message sum
// 12 weight images (set x layer x split), each 128x128 bf16 in HMMA B-fragment order
__device__ __nv_bfloat16 g_Wimg[12 * 16384];

__device__ __forceinline__ float gelu_f(float x) {
    return 0.5f * x * (1.0f + erff(x * 0.70710678118654752f));
}
__device__ __forceinline__ void split_pack(float a, float b, uint32_t& hi, uint32_t& lo) {
    __nv_bfloat16 ah = __float2bfloat16_rn(a);
    __nv_bfloat16 bh = __float2bfloat16_rn(b);
    __nv_bfloat162 hp; hp.x = ah; hp.y = bh;
    __nv_bfloat162 lp;
    lp.x = __float2bfloat16_rn(a - __bfloat162float(ah));
    lp.y = __float2bfloat16_rn(b - __bfloat162float(bh));
    hi = *reinterpret_cast<uint32_t*>(&hp);
    lo = *reinterpret_cast<uint32_t*>(&lp);
}
__device__ __forceinline__ void mma16816(float c[4], const uint32_t a[4],
                                         uint32_t b0, uint32_t b1) {
    asm volatile(
        "mma.sync.aligned.m16n8k16.row.col.f32.bf16.bf16.f32 "
        "{%0,%1,%2,%3}, {%4,%5,%6,%7}, {%8,%9}, {%0,%1,%2,%3};"
        : "+f"(c[0]), "+f"(c[1]), "+f"(c[2]), "+f"(c[3])
        : "r"(a[0]), "r"(a[1]), "r"(a[2]), "r"(a[3]), "r"(b0), "r"(b1));
}

// ---------------------------------------------------------------------------
// Weight prep: 12 images. Source s[k*128+n] = W[k][n]. B-fragment layout for
// mma.m16n8k16 (col-major B): thread lane = (n&7)*4 + t holds k = {t*2,t*2+1}
// (reg b0) and {t*2+8,t*2+9} (reg b1). Chunk per (n8-tile, k-step) = 256 B.
// ---------------------------------------------------------------------------
__global__ void prep_weights(const float* __restrict__ A0, const float* __restrict__ A1,
                             const float* __restrict__ A2, const float* __restrict__ B0,
                             const float* __restrict__ B1, const float* __restrict__ B2) {
    const float* srcs[6] = {A0, A1, A2, B0, B1, B2};
    int img = blockIdx.x;                       // set*6 + layer*2 + split
    int set = img / 6, layer = (img % 6) >> 1, split = img & 1;
    const float* s = srcs[set * 3 + layer];
    __nv_bfloat16* dst = g_Wimg + (size_t)img * 16384;
    for (int e = threadIdx.x; e < 16384; e += blockDim.x) {
        int k = e >> 7, n = e & 127;
        float val = s[e];
        __nv_bfloat16 h = __float2bfloat16_rn(val);
        __nv_bfloat16 outv = split ? __float2bfloat16_rn(val - __bfloat162float(h)) : h;
        int kk = k & 15;
        int t = (kk & 7) >> 1, hi8 = kk >> 3, idx = kk & 1;
        int lane = (n & 7) * 4 + t;
        int chunk = (n >> 3) * 8 + (k >> 4);
        int half_off = chunk * 128 + lane * 4 + hi8 * 2 + idx;   // in bf16 units
        dst[half_off] = outv;
    }
}

// ---------------------------------------------------------------------------
// HMMA edge MLP. Persistent grid=148, 384 threads (12 warps). One node/iter:
// tile 48x128. Warp w: mtile = w>>2 (m16), nchunk = w&3 (n32 = 4 n8-tiles).
// SMEM: 192KB weights (6 images) + A hi/lo bf16 48x(stride 68 words).
// 3-split GEMM: hi@Whi + lo@Whi + hi@Wlo.
// ---------------------------------------------------------------------------
#define A_STRIDE_W 68                 // words per row (136 bf16): conflict-free
#define A_WORDS (KK * A_STRIDE_W)     // 3264 words per split image
#define SMEM_W_BYTES 196608
#define SMEM_EDGE_DYN (SMEM_W_BYTES + 2 * A_WORDS * 4)   // + 26112 = 222720

template <bool EDGE_OUT>
__global__ void __launch_bounds__(384, 1) edge_mma_kernel(
    const float* __restrict__ h_E, const int* __restrict__ E_idx,
    const float* __restrict__ mask_attend, int wset,
    const float* __restrict__ b2v, const float* __restrict__ b3v,
    const float* __restrict__ g3v, const float* __restrict__ b3ln,
    float* __restrict__ outp) {
    extern __shared__ uint32_t smem[];
    uint32_t* smW = smem;                         // 49152 words: 6 images
    uint32_t* smA = smem + (SMEM_W_BYTES / 4);    // hi at 0, lo at +A_WORDS
    float* Fs = (float*)smA;                      // overlay for K-sum (48x132 f32)

    __shared__ int s_idx[KK];
    __shared__ float s_mask[KK];
    __shared__ float s_b2[CC], s_b3[CC], s_g3[CC], s_bl[CC];
    __shared__ float s_red[KK][4][2];

    const int tid = threadIdx.x, lane = tid & 31, wid = tid >> 5;
    const int g = lane >> 2, t = lane & 3;
    const int mtile = wid >> 2, nchunk = wid & 3;
    const int m0 = mtile * 16, n0 = nchunk * 32;
    const int ntg0 = nchunk * 4;                  // first global n8-tile

    {   // copy 192KB of weights for this set
        const float4* src = (const float4*)(g_Wimg + (size_t)wset * 6 * 16384);
        float4* dst = (float4*)smW;
        for (int i = tid; i < 12288; i += 384) dst[i] = src[i];
    }
    if (tid < CC) {
        s_b2[tid] = b2v[tid];
        s_b3[tid] = b3v[tid];
        if (EDGE_OUT) { s_g3[tid] = g3v[tid]; s_bl[tid] = b3ln[tid]; }
    }

    const int r_lo = m0 + g, r_hi = m0 + g + 8;   // this thread's two rows (kk idx)

    for (int node = blockIdx.x; node < BN; node += gridDim.x) {
        __syncthreads();   // previous iteration's SMEM reads complete

        // ---- prologue: split h_E tile into SMEM A hi/lo; fetch idx/mask
        if (tid < KK) {
            s_idx[tid] = E_idx[node * KK + tid];
            s_mask[tid] = mask_attend[node * KK + tid];
        }
        {
            const float4* he4 = (const float4*)(h_E + (size_t)node * (KK * CC));
#pragma unroll
            for (int i = 0; i < 4; ++i) {
                int idx4 = tid + 384 * i;
                float4 v = he4[idx4];
                int row = idx4 >> 5, colw = (idx4 & 31) * 2;   // word col
                uint32_t h0, l0, h1, l1;
                split_pack(v.x, v.y, h0, l0);
                split_pack(v.z, v.w, h1, l1);
                int w = row * A_STRIDE_W + colw;
                smA[w] = h0; smA[w + 1] = h1;
                smA[A_WORDS + w] = l0; smA[A_WORDS + w + 1] = l1;
            }
        }
        __syncthreads();

        for (int layer = 0; layer < 3; ++layer) {
            float acc[4][4];
#pragma unroll
            for (int nt = 0; nt < 4; ++nt)
#pragma unroll
                for (int j = 0; j < 4; ++j) acc[nt][j] = 0.0f;

            const uint2* WH = (const uint2*)(smW + (layer * 2) * 8192);
            const uint2* WL = WH + 4096;
#pragma unroll 2
            for (int ks = 0; ks < 8; ++ks) {
                uint32_t ahi[4], alo[4];
                int aw = r_lo * A_STRIDE_W + ks * 8 + t;
                int aw2 = r_hi * A_STRIDE_W + ks * 8 + t;
                ahi[0] = smA[aw];        ahi[1] = smA[aw2];
                ahi[2] = smA[aw + 4];    ahi[3] = smA[aw2 + 4];
                alo[0] = smA[A_WORDS + aw];     alo[1] = smA[A_WORDS + aw2];
                alo[2] = smA[A_WORDS + aw + 4]; alo[3] = smA[A_WORDS + aw2 + 4];
#pragma unroll
                for (int nt = 0; nt < 4; ++nt) {
                    int chunk = (ntg0 + nt) * 8 + ks;
                    uint2 bh = WH[chunk * 32 + lane];
                    uint2 bl = WL[chunk * 32 + lane];
                    mma16816(acc[nt], ahi, bh.x, bh.y);
                    mma16816(acc[nt], alo, bh.x, bh.y);
                    mma16816(acc[nt], ahi, bl.x, bl.y);
                }
            }
            __syncthreads();   // all A reads done before rewrite

            if (layer < 2) {
                // epilogue: add (Pa+Pc | b2), gelu, re-split into A hi/lo
                int nbr0 = 0, nbr1 = 0;
                if (layer == 0) {
                    int gb = (node >> 11) * NN;
                    nbr0 = gb + s_idx[r_lo];
                    nbr1 = gb + s_idx[r_hi];
                }
#pragma unroll
                for (int nt = 0; nt < 4; ++nt) {
                    int c = n0 + nt * 8 + t * 2;
                    float a0, a1, b0, b1;   // addends row_lo(c,c+1), row_hi(c,c+1)
                    if (layer == 0) {
                        float2 pa = *(const float2*)(g_Pa + (size_t)node * CC + c);
                        float2 p0 = *(const float2*)(g_Pc + (size_t)nbr0 * CC + c);
                        float2 p1 = *(const float2*)(g_Pc + (size_t)nbr1 * CC + c);
                        a0 = pa.x + p0.x; a1 = pa.y + p0.y;
                        b0 = pa.x + p1.x; b1 = pa.y + p1.y;
                    } else {
                        a0 = s_b2[c]; a1 = s_b2[c + 1];
                        b0 = a0; b1 = a1;
                    }
                    float xl0 = gelu_f(acc[nt][0] + a0);
                    float xl1 = gelu_f(acc[nt][1] + a1);
                    float xh0 = gelu_f(acc[nt][2] + b0);
                    float xh1 = gelu_f(acc[nt][3] + b1);
                    uint32_t hh, ll;
                    int w0 = r_lo * A_STRIDE_W + c / 2;
                    int w1 = r_hi * A_STRIDE_W + c / 2;
                    split_pack(xl0, xl1, hh, ll);
                    smA[w0] = hh; smA[A_WORDS + w0] = ll;
                    split_pack(xh0, xh1, hh, ll);
                    smA[w1] = hh; smA[A_WORDS + w1] = ll;
                }
                __syncthreads();
            } else if (!EDGE_OUT) {
                // masked message -> SMEM Fs, then column reduce -> g_dh
                float mlo = s_mask[r_lo], mhi = s_mask[r_hi];
#pragma unroll
                for (int nt = 0; nt < 4; ++nt) {
                    int c = n0 + nt * 8 + t * 2;
                    float2 v0, v1;
                    v0.x = mlo * (acc[nt][0] + s_b3[c]);
                    v0.y = mlo * (acc[nt][1] + s_b3[c + 1]);
                    v1.x = mhi * (acc[nt][2] + s_b3[c]);
                    v1.y = mhi * (acc[nt][3] + s_b3[c + 1]);
                    *(float2*)(Fs + r_lo * 132 + c) = v0;
                    *(float2*)(Fs + r_hi * 132 + c) = v1;
                }
                __syncthreads();
                if (tid < CC) {
                    float s = 0.0f;
#pragma unroll
                    for (int r = 0; r < KK; ++r) s += Fs[r * 132 + tid];
                    g_dh[(size_t)node * CC + tid] = s;
                }
            } else {
                // v = h_E + msg + b3 ; per-row LayerNorm -> out
                const float* he = h_E + (size_t)node * (KK * CC);
                float v[4][4];
                float sl = 0.0f, ql = 0.0f, sh = 0.0f, qh = 0.0f;
#pragma unroll
                for (int nt = 0; nt < 4; ++nt) {
                    int c = n0 + nt * 8 + t * 2;
                    float2 e0 = *(const float2*)(he + r_lo * CC + c);
                    float2 e1 = *(const float2*)(he + r_hi * CC + c);
                    v[nt][0] = acc[nt][0] + s_b3[c] + e0.x;
                    v[nt][1] = acc[nt][1] + s_b3[c + 1] + e0.y;
                    v[nt][2] = acc[nt][2] + s_b3[c] + e1.x;
                    v[nt][3] = acc[nt][3] + s_b3[c + 1] + e1.y;
                    sl += v[nt][0] + v[nt][1]; ql += v[nt][0] * v[nt][0] + v[nt][1] * v[nt][1];
                    sh += v[nt][2] + v[nt][3]; qh += v[nt][2] * v[nt][2] + v[nt][3] * v[nt][3];
                }
                // quad reduce (lanes g*4..g*4+3)
#pragma unroll
                for (int off = 1; off <= 2; off <<= 1) {
                    sl += __shfl_xor_sync(0xffffffffu, sl, off);
                    ql += __shfl_xor_sync(0xffffffffu, ql, off);
                    sh += __shfl_xor_sync(0xffffffffu, sh, off);
                    qh += __shfl_xor_sync(0xffffffffu, qh, off);
                }
                if (t == 0) {
                    s_red[r_lo][nchunk][0] = sl; s_red[r_lo][nchunk][1] = ql;
                    s_red[r_hi][nchunk][0] = sh; s_red[r_hi][nchunk][1] = qh;
                }
                __syncthreads();
                float S0 = 0, Q0 = 0, S1 = 0, Q1 = 0;
#pragma unroll
                for (int w = 0; w < 4; ++w) {
                    S0 += s_red[r_lo][w][0]; Q0 += s_red[r_lo][w][1];
                    S1 += s_red[r_hi][w][0]; Q1 += s_red[r_hi][w][1];
                }
                float m0f = S0 * (1.0f / 128.0f);
                float rs0 = rsqrtf(Q0 * (1.0f / 128.0f) - m0f * m0f + EPSLN);
                float m1f = S1 * (1.0f / 128.0f);
                float rs1 = rsqrtf(Q1 * (1.0f / 128.0f) - m1f * m1f + EPSLN);
                float* op = outp + (size_t)node * (KK * CC);
#pragma unroll
                for (int nt = 0; nt < 4; ++nt) {
                    int c = n0 + nt * 8 + t * 2;
                    float2 o0, o1;
                    o0.x = s_g3[c] * (v[nt][0] - m0f) * rs0 + s_bl[c];
                    o0.y = s_g3[c + 1] * (v[nt][1] - m0f) * rs0 + s_bl[c + 1];
                    o1.x = s_g3[c] * (v[nt][2] - m1f) * rs1 + s_bl[c];
                    o1.y = s_g3[c + 1] * (v[nt][3] - m1f) * rs1 + s_bl[c + 1];
                    *(float2*)(op + r_lo * CC + c) = o0;
                    *(float2*)(op + r_hi * CC + c) = o1;
                }
            }
        }
    }
}

// ---------------------------------------------------------------------------
// Scalar node precompute + FFN (proven baseline).
// ---------------------------------------------------------------------------
template <int R>
__device__ __forceinline__ void mm_tile(float acc[R][4], const float* Xs, int xstride4,
                                        const float* Ws, int r0, int lane) {
    const float4* X4 = (const float4*)Xs;
    const float4* W4 = (const float4*)Ws;
#pragma unroll 4
    for (int kq = 0; kq < 32; ++kq) {
        float4 w0 = W4[(4 * kq + 0) * 32 + lane];
        float4 w1 = W4[(4 * kq + 1) * 32 + lane];
        float4 w2 = W4[(4 * kq + 2) * 32 + lane];
        float4 w3 = W4[(4 * kq + 3) * 32 + lane];
#pragma unroll
        for (int i = 0; i < R; ++i) {
            float4 x = X4[(r0 + i) * xstride4 + kq];
            acc[i][0] = fmaf(x.x, w0.x, acc[i][0]); acc[i][1] = fmaf(x.x, w0.y, acc[i][1]);
            acc[i][2] = fmaf(x.x, w0.z, acc[i][2]); acc[i][3] = fmaf(x.x, w0.w, acc[i][3]);
            acc[i][0] = fmaf(x.y, w1.x, acc[i][0]); acc[i][1] = fmaf(x.y, w1.y, acc[i][1]);
            acc[i][2] = fmaf(x.y, w1.z, acc[i][2]); acc[i][3] = fmaf(x.y, w1.w, acc[i][3]);
            acc[i][0] = fmaf(x.z, w2.x, acc[i][0]); acc[i][1] = fmaf(x.z, w2.y, acc[i][1]);
            acc[i][2] = fmaf(x.z, w2.z, acc[i][2]); acc[i][3] = fmaf(x.z, w2.w, acc[i][3]);
            acc[i][0] = fmaf(x.w, w3.x, acc[i][0]); acc[i][1] = fmaf(x.w, w3.y, acc[i][1]);
            acc[i][2] = fmaf(x.w, w3.z, acc[i][2]); acc[i][3] = fmaf(x.w, w3.w, acc[i][3]);
        }
    }
}

__global__ void __launch_bounds__(512) nodepre_kernel(
    const float* __restrict__ hV, const float* __restrict__ W1,
    const float* __restrict__ b1) {
    extern __shared__ float sm[];
    float* Vs = sm;
    float* Ws = sm + 4096;
    int tid = threadIdx.x, lane = tid & 31, warp = tid >> 5;
    size_t base = (size_t)blockIdx.x * 32 * CC;
    {
        const float4* src = (const float4*)(hV + base);
        float4* dst = (float4*)Vs;
#pragma unroll
        for (int e = 0; e < 2; ++e) dst[tid + 512 * e] = src[tid + 512 * e];
    }
    {
        const float4* src = (const float4*)W1;
        float4* dst = (float4*)Ws;
#pragma unroll
        for (int e = 0; e < 8; ++e) dst[tid + 512 * e] = src[tid + 512 * e];
    }
    __syncthreads();
    int r0 = warp * 2, c0 = lane * 4;
    float acc[2][4];
#pragma unroll
    for (int j = 0; j < 4; ++j) { float b = b1[c0 + j]; acc[0][j] = b; acc[1][j] = b; }
    mm_tile<2>(acc, Vs, 32, Ws, r0, lane);
#pragma unroll
    for (int i = 0; i < 2; ++i)
#pragma unroll
        for (int j = 0; j < 4; ++j)
            g_Pa[base + (size_t)(r0 + i) * CC + c0 + j] = acc[i][j];
    __syncthreads();
    {
        const float4* src = (const float4*)(W1 + 2 * CC * CC);
        float4* dst = (float4*)Ws;
#pragma unroll
        for (int e = 0; e < 8; ++e) dst[tid + 512 * e] = src[tid + 512 * e];
    }
    __syncthreads();
#pragma unroll
    for (int i = 0; i < 2; ++i)
#pragma unroll
        for (int j = 0; j < 4; ++j) acc[i][j] = 0.0f;
    mm_tile<2>(acc, Vs, 32, Ws, r0, lane);
#pragma unroll
    for (int i = 0; i < 2; ++i)
#pragma unroll
        for (int j = 0; j < 4; ++j)
            g_Pc[base + (size_t)(r0 + i) * CC + c0 + j] = acc[i][j];
}

__global__ void __launch_bounds__(512) ffn_kernel(
    const float* __restrict__ hV,
    const float* __restrict__ Win_w, const float* __restrict__ Win_b,
    const float* __restrict__ Wout_w, const float* __restrict__ Wout_b,
    const float* __restrict__ g1, const float* __restrict__ b1,
    const float* __restrict__ g2, const float* __restrict__ b2,
    const float* __restrict__ mask_V, float* __restrict__ out) {
    extern __shared__ float sm[];
    float* V1s = sm;
    float* Ts = sm + 4096;
    float* Ws = sm + 4096 + 16384;
    int tid = threadIdx.x, lane = tid & 31, warp = tid >> 5;
    size_t base = (size_t)blockIdx.x * 32 * CC;
    int c0 = lane * 4, r0 = warp * 2;
#pragma unroll
    for (int i = 0; i < 2; ++i) {
        int r = r0 + i;
        float4 xv = *(const float4*)(hV + base + (size_t)r * CC + c0);
        float4 dv = *(const float4*)(&g_dh[base + (size_t)r * CC + c0]);
        float x0 = xv.x + dv.x * INV_SCALE, x1 = xv.y + dv.y * INV_SCALE;
        float x2 = xv.z + dv.z * INV_SCALE, x3 = xv.w + dv.w * INV_SCALE;
        float s = x0 + x1 + x2 + x3;
        float q = x0 * x0 + x1 * x1 + x2 * x2 + x3 * x3;
#pragma unroll
        for (int off = 16; off; off >>= 1) {
            s += __shfl_xor_sync(0xffffffffu, s, off);
            q += __shfl_xor_sync(0xffffffffu, q, off);
        }
        float mean = s * (1.0f / 128.0f);
        float var = q * (1.0f / 128.0f) - mean * mean;
        float rs = rsqrtf(var + EPSLN);
        float4 o;
        o.x = g1[c0 + 0] * (x0 - mean) * rs + b1[c0 + 0];
        o.y = g1[c0 + 1] * (x1 - mean) * rs + b1[c0 + 1];
        o.z = g1[c0 + 2] * (x2 - mean) * rs + b1[c0 + 2];
        o.w = g1[c0 + 3] * (x3 - mean) * rs + b1[c0 + 3];
        *(float4*)(V1s + r * CC + c0) = o;
    }
    __syncthreads();
    for (int ct = 0; ct < 4; ++ct) {
        if (ct) __syncthreads();
        for (int e = tid; e < 4096; e += 512) {
            int k = e >> 5, cq = e & 31;
            ((float4*)Ws)[e] = ((const float4*)Win_w)[k * 128 + ct * 32 + cq];
        }
        __syncthreads();
        float acc[2][4];
#pragma unroll
        for (int j = 0; j < 4; ++j) {
            float b = Win_b[ct * 128 + c0 + j];
            acc[0][j] = b; acc[1][j] = b;
        }
        mm_tile<2>(acc, V1s, 32, Ws, r0, lane);
#pragma unroll
        for (int i = 0; i < 2; ++i)
#pragma unroll
            for (int j = 0; j < 4; ++j)
                Ts[(r0 + i) * FFD + ct * 128 + c0 + j] = gelu_f(acc[i][j]);
    }
    __syncthreads();
    float acc[2][4];
#pragma unroll
    for (int j = 0; j < 4; ++j) {
        float b = Wout_b[c0 + j];
        acc[0][j] = b; acc[1][j] = b;
    }
    for (int kt = 0; kt < 4; ++kt) {
        if (kt) __syncthreads();
        for (int e = tid; e < 4096; e += 512)
            ((float4*)Ws)[e] = ((const float4*)Wout_w)[kt * 4096 + e];
        __syncthreads();
        mm_tile<2>(acc, Ts + kt * 128, 128, Ws, r0, lane);
    }
#pragma unroll
    for (int i = 0; i < 2; ++i) {
        int r = r0 + i;
        float v0 = V1s[r * CC + c0 + 0] + acc[i][0];
        float v1 = V1s[r * CC + c0 + 1] + acc[i][1];
        float v2 = V1s[r * CC + c0 + 2] + acc[i][2];
        float v3 = V1s[r * CC + c0 + 3] + acc[i][3];
        float s = v0 + v1 + v2 + v3;
        float q = v0 * v0 + v1 * v1 + v2 * v2 + v3 * v3;
#pragma unroll
        for (int off = 16; off; off >>= 1) {
            s += __shfl_xor_sync(0xffffffffu, s, off);
            q += __shfl_xor_sync(0xffffffffu, q, off);
        }
        float mean = s * (1.0f / 128.0f);
        float var = q * (1.0f / 128.0f) - mean * mean;
        float rs = rsqrtf(var + EPSLN);
        float mv = mask_V[blockIdx.x * 32 + r];
        float4 o;
        o.x = (g2[c0 + 0] * (v0 - mean) * rs + b2[c0 + 0]) * mv;
        o.y = (g2[c0 + 1] * (v1 - mean) * rs + b2[c0 + 1]) * mv;
        o.z = (g2[c0 + 2] * (v2 - mean) * rs + b2[c0 + 2]) * mv;
        o.w = (g2[c0 + 3] * (v3 - mean) * rs + b2[c0 + 3]) * mv;
        *(float4*)(out + base + (size_t)r * CC + c0) = o;
    }
}

// ---------------------------------------------------------------------------
extern "C" void kernel_launch(void* const* d_in, const int* in_sizes, int n_in,
                              void* d_out, int out_size) {
    const float* h_V = (const float*)d_in[0];
    const float* h_E = (const float*)d_in[1];
    const int* E_idx = (const int*)d_in[2];
    const float* mask_V = (const float*)d_in[3];
    const float* mask_attend = (const float*)d_in[4];
    const float* W1_w = (const float*)d_in[5];
    const float* W1_b = (const float*)d_in[6];
    const float* W2_w = (const float*)d_in[7];
    const float* W2_b = (const float*)d_in[8];
    const float* W3_w = (const float*)d_in[9];
    const float* W3_b = (const float*)d_in[10];
    const float* W11_w = (const float*)d_in[11];
    const float* W11_b = (const float*)d_in[12];
    const float* W12_w = (const float*)d_in[13];
    const float* W12_b = (const float*)d_in[14];
    const float* W13_w = (const float*)d_in[15];
    const float* W13_b = (const float*)d_in[16];
    const float* Win_w = (const float*)d_in[17];
    const float* Win_b = (const float*)d_in[18];
    const float* Wout_w = (const float*)d_in[19];
    const float* Wout_b = (const float*)d_in[20];
    const float* g1 = (const float*)d_in[21];
    const float* b1 = (const float*)d_in[22];
    const float* g2 = (const float*)d_in[23];
    const float* b2 = (const float*)d_in[24];
    const float* g3 = (const float*)d_in[25];
    const float* b3 = (const float*)d_in[26];

    float* out_hV = (float*)d_out;
    float* out_hE = out_hV + (size_t)BN * CC;

    const int SMEM_PRE = (4096 + 16384) * 4;
    const int SMEM_FFN = (4096 + 16384 + 16384) * 4;

    cudaFuncSetAttribute(nodepre_kernel, cudaFuncAttributeMaxDynamicSharedMemorySize, SMEM_PRE);
    cudaFuncSetAttribute(ffn_kernel, cudaFuncAttributeMaxDynamicSharedMemorySize, SMEM_FFN);
    cudaFuncSetAttribute(edge_mma_kernel<false>, cudaFuncAttributeMaxDynamicSharedMemorySize, SMEM_EDGE_DYN);
    cudaFuncSetAttribute(edge_mma_kernel<true>, cudaFuncAttributeMaxDynamicSharedMemorySize, SMEM_EDGE_DYN);

    // 0) weight fragment images (W1b / W11b = middle 128x128 slabs)
    prep_weights<<<12, 256>>>(W1_w + CC * CC, W2_w, W3_w, W11_w + CC * CC, W12_w, W13_w);
    // 1) node precompute #1
    nodepre_kernel<<<BN / 32, 512, SMEM_PRE>>>(h_V, W1_w, W1_b);
    // 2) edge MLP #1 (HMMA) -> masked K-sum -> g_dh
    edge_mma_kernel<false><<<148, 384, SMEM_EDGE_DYN>>>(h_E, E_idx, mask_attend, 0,
                                                        W2_b, W3_b, g3, b3, out_hE);
    // 3) node residual + LN1 + FFN + LN2 + mask
    ffn_kernel<<<BN / 32, 512, SMEM_FFN>>>(h_V, Win_w, Win_b, Wout_w, Wout_b,
                                           g1, b1, g2, b2, mask_V, out_hV);
    // 4) node precompute #2 (updated h_V)
    nodepre_kernel<<<BN / 32, 512, SMEM_PRE>>>(out_hV, W11_w, W11_b);
    // 5) edge MLP #2 (HMMA) + residual + LN3 -> out_hE
    edge_mma_kernel<true><<<148, 384, SMEM_EDGE_DYN>>>(h_E, E_idx, mask_attend, 1,
                                                       W12_b, W13_b, g3, b3, out_hE);
}